// round 3
// baseline (speedup 1.0000x reference)
#include <cuda_runtime.h>
#include <cuda_bf16.h>
#include <math.h>

// Problem constants
#define BB 128
#define LL 200
#define D2 1024   // 2*SH
#define EH 512
#define AA 512
#define TT 3

// -------- device scratch (allocation-free rule: __device__ globals) --------
__device__ float g_dproj[(size_t)BB * LL * AA];   // 52.4 MB  [m][a], m=b*L+l
__device__ float g_xT[1536 * BB];                 // [k][b]: rows 0..1023 = s_prev, 1024..1535 = h
__device__ float g_g2T[2048 * BB];                // [j][b]: 0..1023 rz(gx+gh), 1024..1535 xn, 1536..2047 hn
__device__ float g_q[BB * AA];                    // [b][a]
__device__ float g_WA[1024 * 1536];               // packed [w_ih_row | w_hh_row] for j<1024
__device__ int   g_idx[BB * TT];

// -------------------------------------------------------------------------
// Pack WA[j][0:1024]=w_ih[j], WA[j][1024:1536]=w_hh[j]  (j<1024)
__global__ void k_pack(const float* __restrict__ w_ih, const float* __restrict__ w_hh) {
    int j = blockIdx.x;                 // 1024 blocks
    int tid = threadIdx.x;              // 128 threads
    const float4* sih = reinterpret_cast<const float4*>(w_ih + (size_t)j * 1024);
    const float4* shh = reinterpret_cast<const float4*>(w_hh + (size_t)j * 512);
    float4* dst = reinterpret_cast<float4*>(g_WA + (size_t)j * 1536);
    for (int i = tid; i < 256; i += 128) dst[i] = sih[i];
    for (int i = tid; i < 128; i += 128) dst[256 + i] = shh[i];
}

// -------------------------------------------------------------------------
// h0[b,e] = tanh(sent[b,0,512:] @ h0_w[e,:] + h0_b[e]) -> xT rows 1024..1535
// also zero xT rows 0..1023 (s_prev = 0 for iter 0)
__global__ void k_init(const float* __restrict__ sent, const float* __restrict__ h0w,
                       const float* __restrict__ h0b) {
    int b = blockIdx.x;                 // 128 blocks
    int tid = threadIdx.x;              // 256 threads
    __shared__ float xs[512];
    const float* lb = sent + (size_t)b * LL * D2 + 512;
    for (int i = tid; i < 512; i += 256) xs[i] = lb[i];
    for (int k = tid; k < 1024; k += 256) g_xT[(size_t)k * BB + b] = 0.f;
    __syncthreads();
    for (int e = tid; e < 512; e += 256) {
        const float4* wr = reinterpret_cast<const float4*>(h0w + (size_t)e * 512);
        float s = 0.f;
        #pragma unroll 8
        for (int i = 0; i < 128; i++) {
            float4 w = wr[i];
            float4 x = *reinterpret_cast<const float4*>(&xs[i * 4]);
            s = fmaf(w.x, x.x, s); s = fmaf(w.y, x.y, s);
            s = fmaf(w.z, x.z, s); s = fmaf(w.w, x.w, s);
        }
        g_xT[(size_t)(1024 + e) * BB + b] = tanhf(s + h0b[e]);
    }
}

// -------------------------------------------------------------------------
// d_proj = sent @ wd^T + bd : SGEMM M=25600 N=512 K=1024, C[m][n] row-major.
// 128x128 block tile, k-chunk 8, 256 threads, 8x8 per thread, double buffered.
__global__ __launch_bounds__(256) void k_dproj(const float* __restrict__ Ag,
                                               const float* __restrict__ Wg,
                                               const float* __restrict__ bd,
                                               float* __restrict__ C) {
    __shared__ float As[2][8][132];
    __shared__ float Bs[2][8][132];
    const int m0 = blockIdx.x * 128;
    const int n0 = blockIdx.y * 128;
    const int tid = threadIdx.x;
    const int lrow = tid >> 1;
    const int lq = (tid & 1);           // float4 quarter: k offset lq*4
    const float4* Aro = reinterpret_cast<const float4*>(Ag + (size_t)(m0 + lrow) * 1024);
    const float4* Wro = reinterpret_cast<const float4*>(Wg + (size_t)(n0 + lrow) * 1024);
    const int tx = tid & 15, ty = tid >> 4;

    float acc[8][8];
    #pragma unroll
    for (int i = 0; i < 8; i++)
        #pragma unroll
        for (int j = 0; j < 8; j++) acc[i][j] = 0.f;

    float4 a_ld = Aro[lq];
    float4 w_ld = Wro[lq];
    As[0][lq * 4 + 0][lrow] = a_ld.x; As[0][lq * 4 + 1][lrow] = a_ld.y;
    As[0][lq * 4 + 2][lrow] = a_ld.z; As[0][lq * 4 + 3][lrow] = a_ld.w;
    Bs[0][lq * 4 + 0][lrow] = w_ld.x; Bs[0][lq * 4 + 1][lrow] = w_ld.y;
    Bs[0][lq * 4 + 2][lrow] = w_ld.z; Bs[0][lq * 4 + 3][lrow] = w_ld.w;
    __syncthreads();

    int buf = 0;
    for (int k0 = 0; k0 < 1024; k0 += 8) {
        const bool more = (k0 + 8) < 1024;
        if (more) {
            a_ld = Aro[((k0 + 8) >> 2) + lq];
            w_ld = Wro[((k0 + 8) >> 2) + lq];
        }
        #pragma unroll
        for (int kk = 0; kk < 8; kk++) {
            float4 a0 = *reinterpret_cast<const float4*>(&As[buf][kk][ty * 4]);
            float4 a1 = *reinterpret_cast<const float4*>(&As[buf][kk][64 + ty * 4]);
            float4 b0 = *reinterpret_cast<const float4*>(&Bs[buf][kk][tx * 4]);
            float4 b1 = *reinterpret_cast<const float4*>(&Bs[buf][kk][64 + tx * 4]);
            float av[8] = {a0.x, a0.y, a0.z, a0.w, a1.x, a1.y, a1.z, a1.w};
            float bv[8] = {b0.x, b0.y, b0.z, b0.w, b1.x, b1.y, b1.z, b1.w};
            #pragma unroll
            for (int i = 0; i < 8; i++)
                #pragma unroll
                for (int j = 0; j < 8; j++)
                    acc[i][j] = fmaf(av[i], bv[j], acc[i][j]);
        }
        if (more) {
            int nb = buf ^ 1;
            As[nb][lq * 4 + 0][lrow] = a_ld.x; As[nb][lq * 4 + 1][lrow] = a_ld.y;
            As[nb][lq * 4 + 2][lrow] = a_ld.z; As[nb][lq * 4 + 3][lrow] = a_ld.w;
            Bs[nb][lq * 4 + 0][lrow] = w_ld.x; Bs[nb][lq * 4 + 1][lrow] = w_ld.y;
            Bs[nb][lq * 4 + 2][lrow] = w_ld.z; Bs[nb][lq * 4 + 3][lrow] = w_ld.w;
            __syncthreads();
            buf = nb;
        }
    }

    float bn[8];
    #pragma unroll
    for (int j = 0; j < 4; j++) {
        bn[j]     = bd[n0 + tx * 4 + j];
        bn[4 + j] = bd[n0 + 64 + tx * 4 + j];
    }
    #pragma unroll
    for (int i = 0; i < 8; i++) {
        int m = m0 + ((i < 4) ? (ty * 4 + i) : (64 + ty * 4 + i - 4));
        float* crow = C + (size_t)m * 512 + n0;
        float4 v0 = make_float4(acc[i][0] + bn[0], acc[i][1] + bn[1],
                                acc[i][2] + bn[2], acc[i][3] + bn[3]);
        float4 v1 = make_float4(acc[i][4] + bn[4], acc[i][5] + bn[5],
                                acc[i][6] + bn[6], acc[i][7] + bn[7]);
        *reinterpret_cast<float4*>(crow + tx * 4) = v0;
        *reinterpret_cast<float4*>(crow + 64 + tx * 4) = v1;
    }
}

// -------------------------------------------------------------------------
// Small "tall-skinny" GEMM body: out[j][b] += sum_k W[j][k] * xT[k][b].
// Block: 256 threads = (b = tid&127) x (jj = tid>>7 in {0,1}); JT = 2*JPT j's.
template <int JPT>
__device__ __forceinline__ void gemm_cols(const float* __restrict__ W, int K,
                                          const float* __restrict__ xcol,
                                          int b, int jj, float acc[JPT], float* Ws) {
    const int JT = 2 * JPT;
    #pragma unroll
    for (int u = 0; u < JPT; u++) acc[u] = 0.f;
    for (int kc = 0; kc < K; kc += 64) {
        __syncthreads();
        for (int i = threadIdx.x; i < JT * 16; i += blockDim.x) {
            int j = i >> 4, kq = i & 15;
            *reinterpret_cast<float4*>(Ws + j * 64 + kq * 4) =
                *reinterpret_cast<const float4*>(W + (size_t)j * K + kc + kq * 4);
        }
        __syncthreads();
        #pragma unroll 4
        for (int k = 0; k < 64; k += 4) {
            float x0 = xcol[(size_t)(kc + k + 0) * BB + b];
            float x1 = xcol[(size_t)(kc + k + 1) * BB + b];
            float x2 = xcol[(size_t)(kc + k + 2) * BB + b];
            float x3 = xcol[(size_t)(kc + k + 3) * BB + b];
            #pragma unroll
            for (int u = 0; u < JPT; u++) {
                float4 w = *reinterpret_cast<const float4*>(Ws + (jj * JPT + u) * 64 + k);
                acc[u] = fmaf(w.x, x0, acc[u]);
                acc[u] = fmaf(w.y, x1, acc[u]);
                acc[u] = fmaf(w.z, x2, acc[u]);
                acc[u] = fmaf(w.w, x3, acc[u]);
            }
        }
    }
}

// gates: segA (j<1024): combined (gx+gh) over K=1536 with packed WA.
//        segB: xn rows (w_ih rows 1024..1535, K=1024, x = s_prev part)
//        segC: hn rows (w_hh rows 1024..1535, K=512,  x = h part)
__global__ __launch_bounds__(256) void k_gates(const float* __restrict__ w_ih,
                                               const float* __restrict__ w_hh,
                                               const float* __restrict__ b_ih,
                                               const float* __restrict__ b_hh) {
    __shared__ float Ws[16 * 64];
    const int bid = blockIdx.x;          // 128 blocks
    const int tid = threadIdx.x;
    const int b = tid & 127, jj = tid >> 7;
    const float* W; const float* xcol; const float* bias1; const float* bias2 = nullptr;
    int K, outj;
    if (bid < 64) {
        int j0 = bid * 16;
        W = g_WA + (size_t)j0 * 1536; K = 1536; xcol = g_xT;
        bias1 = b_ih + j0; bias2 = b_hh + j0; outj = j0;
    } else if (bid < 96) {
        int j0 = 1024 + (bid - 64) * 16;
        W = w_ih + (size_t)j0 * 1024; K = 1024; xcol = g_xT;
        bias1 = b_ih + j0; outj = j0;
    } else {
        int j0 = 1024 + (bid - 96) * 16;
        W = w_hh + (size_t)j0 * 512; K = 512; xcol = g_xT + (size_t)1024 * BB;
        bias1 = b_hh + j0; outj = 512 + j0;   // rows 1536..2047
    }
    float acc[8];
    gemm_cols<8>(W, K, xcol, b, jj, acc, Ws);
    #pragma unroll
    for (int u = 0; u < 8; u++) {
        int jl = jj * 8 + u;
        float v = acc[u] + bias1[jl];
        if (bias2) v += bias2[jl];
        g_g2T[(size_t)(outj + jl) * BB + b] = v;
    }
}

// GRU combine: h' = (1-z)*n + z*h  (h lives in xT rows 1024..1535, in place)
__global__ void k_comb() {
    int gid = blockIdx.x * blockDim.x + threadIdx.x;   // 65536
    if (gid >= BB * EH) return;
    int b = gid & 127, e = gid >> 7;
    float rg = g_g2T[(size_t)e * BB + b];
    float zg = g_g2T[(size_t)(512 + e) * BB + b];
    float xn = g_g2T[(size_t)(1024 + e) * BB + b];
    float hn = g_g2T[(size_t)(1536 + e) * BB + b];
    float hv = g_xT[(size_t)(1024 + e) * BB + b];
    float r = 1.f / (1.f + expf(-rg));
    float z = 1.f / (1.f + expf(-zg));
    float n = tanhf(fmaf(r, hn, xn));
    g_xT[(size_t)(1024 + e) * BB + b] = fmaf(1.f - z, n, z * hv);
}

// q[b][a] = h' @ wq[a]^T + bq[a]
__global__ __launch_bounds__(256) void k_q(const float* __restrict__ wq,
                                           const float* __restrict__ bq) {
    __shared__ float Ws[8 * 64];
    const int j0 = blockIdx.x * 8;       // 64 blocks
    const int tid = threadIdx.x;
    const int b = tid & 127, jj = tid >> 7;
    float acc[4];
    gemm_cols<4>(wq + (size_t)j0 * 512, 512, g_xT + (size_t)1024 * BB, b, jj, acc, Ws);
    #pragma unroll
    for (int u = 0; u < 4; u++) {
        int jl = jj * 4 + u;
        g_q[(size_t)b * 512 + j0 + jl] = acc[u] + bq[j0 + jl];
    }
}

// score[b,l] = ws . tanh(q[b] + d_proj[b,l]) + bs, with mask -> out scores
__global__ __launch_bounds__(256) void k_score(const float* __restrict__ ws,
                                               const float* __restrict__ bsp,
                                               int t, float* __restrict__ outs) {
    const int b = blockIdx.x / 25;
    const int lg = blockIdx.x % 25;
    const int w = threadIdx.x >> 5, lane = threadIdx.x & 31;
    const int l = lg * 8 + w;
    const float4* dp = reinterpret_cast<const float4*>(g_dproj + (size_t)(b * LL + l) * AA);
    const float4* qv = reinterpret_cast<const float4*>(g_q + (size_t)b * AA);
    const float4* wv = reinterpret_cast<const float4*>(ws);
    float acc = 0.f;
    #pragma unroll
    for (int i = 0; i < 4; i++) {
        float4 d = dp[lane + 32 * i];
        float4 q = qv[lane + 32 * i];
        float4 s = wv[lane + 32 * i];
        acc = fmaf(s.x, tanhf(d.x + q.x), acc);
        acc = fmaf(s.y, tanhf(d.y + q.y), acc);
        acc = fmaf(s.z, tanhf(d.z + q.z), acc);
        acc = fmaf(s.w, tanhf(d.w + q.w), acc);
    }
    #pragma unroll
    for (int off = 16; off; off >>= 1) acc += __shfl_xor_sync(0xffffffffu, acc, off);
    if (lane == 0) {
        float s = acc + bsp[0];
        for (int tt = 0; tt < t; tt++)
            if (g_idx[b * TT + tt] == l) s = -1000000.0f;
        outs[((size_t)b * TT + t) * LL + l] = s;
    }
}

// argmax per b (first-max tie break), record idx, gather selected sentence
__global__ void k_argmax(int t, const float* __restrict__ sent,
                         const float* __restrict__ outs, float* __restrict__ out_sel) {
    const int b = blockIdx.x, tid = threadIdx.x;   // 128 blocks x 256
    const float* sc = outs + ((size_t)b * TT + t) * LL;
    float bv = -3.0e38f; int bi = 0;
    for (int l = tid; l < LL; l += 256) {
        float v = sc[l];
        if (v > bv) { bv = v; bi = l; }
    }
    __shared__ float sv[256]; __shared__ int si[256];
    sv[tid] = bv; si[tid] = bi; __syncthreads();
    for (int s = 128; s > 0; s >>= 1) {
        if (tid < s) {
            if (sv[tid + s] > sv[tid] || (sv[tid + s] == sv[tid] && si[tid + s] < si[tid])) {
                sv[tid] = sv[tid + s]; si[tid] = si[tid + s];
            }
        }
        __syncthreads();
    }
    const int idx = si[0];
    if (tid == 0) { g_idx[b * TT + t] = idx; out_sel[b * TT + t] = (float)idx; }
    const float* srow = sent + ((size_t)(b * LL) + idx) * D2;
    for (int k = tid; k < D2; k += 256) g_xT[(size_t)k * BB + b] = srow[k];
}

// -------------------------------------------------------------------------
extern "C" void kernel_launch(void* const* d_in, const int* in_sizes, int n_in,
                              void* d_out, int out_size) {
    const float* sent = (const float*)d_in[0];
    const float* h0w  = (const float*)d_in[1];
    const float* h0b  = (const float*)d_in[2];
    const float* w_ih = (const float*)d_in[3];
    const float* w_hh = (const float*)d_in[4];
    const float* b_ih = (const float*)d_in[5];
    const float* b_hh = (const float*)d_in[6];
    const float* wq   = (const float*)d_in[7];
    const float* bq   = (const float*)d_in[8];
    const float* wd   = (const float*)d_in[9];
    const float* bd   = (const float*)d_in[10];
    const float* ws   = (const float*)d_in[11];
    const float* bsp  = (const float*)d_in[12];
    (void)in_sizes; (void)n_in; (void)out_size;

    float* out = (float*)d_out;
    float* out_scores = out;                      // B*T*L floats
    float* out_sel = out + (size_t)BB * TT * LL;  // B*T floats (indices as float)

    float* dproj_ptr = nullptr;
    cudaGetSymbolAddress((void**)&dproj_ptr, g_dproj);

    k_pack<<<1024, 128>>>(w_ih, w_hh);
    k_init<<<BB, 256>>>(sent, h0w, h0b);
    k_dproj<<<dim3(200, 4), 256>>>(sent, wd, bd, dproj_ptr);
    for (int t = 0; t < TT; t++) {
        k_gates<<<128, 256>>>(w_ih, w_hh, b_ih, b_hh);
        k_comb<<<256, 256>>>();
        k_q<<<64, 256>>>(wq, bq);
        k_score<<<BB * 25, 256>>>(ws, bsp, t, out_scores);
        k_argmax<<<BB, 256>>>(t, sent, out_scores, out_sel);
    }
}

// round 4
// speedup vs baseline: 1.4015x; 1.4015x over previous
#include <cuda_runtime.h>
#include <cuda_bf16.h>
#include <math.h>

// Problem constants
#define BB 128
#define LL 200
#define D2 1024   // 2*SH
#define EH 512
#define AA 512
#define TT 3

// -------- device scratch (allocation-free rule: __device__ globals) --------
__device__ float g_dproj[(size_t)BB * LL * AA];   // 52.4 MB  [m][a], m=b*L+l
__device__ float g_xT[1536 * BB];                 // [k][b]: rows 0..1023 = s_prev, 1024..1535 = h
__device__ float g_part[4 * 2048 * BB];           // split-K partials [ks][row][b]
__device__ float g_qpart[4 * BB * AA];            // split-K partials for q [ks][b][a]
__device__ float g_q[BB * AA];                    // [b][a]
__device__ float g_WA[1024 * 1536];               // packed [w_ih_row | w_hh_row] for j<1024
__device__ int   g_idx[BB * TT];

// ---------------- f32x2 packed-FMA helpers (sm_103a FFMA2) ----------------
__device__ __forceinline__ unsigned long long pk2(float lo, float hi) {
    unsigned long long r;
    asm("mov.b64 %0, {%1,%2};" : "=l"(r) : "f"(lo), "f"(hi));
    return r;
}
__device__ __forceinline__ void ffma2(unsigned long long& d, unsigned long long a,
                                      unsigned long long b) {
    asm("fma.rn.f32x2 %0, %1, %2, %0;" : "+l"(d) : "l"(a), "l"(b));
}
__device__ __forceinline__ float2 upk(unsigned long long v) {
    float2 f;
    asm("mov.b64 {%0,%1}, %2;" : "=f"(f.x), "=f"(f.y) : "l"(v));
    return f;
}
__device__ __forceinline__ float tanh_fast(float x) {
    float y;
    asm("tanh.approx.f32 %0, %1;" : "=f"(y) : "f"(x));
    return y;
}

// -------------------------------------------------------------------------
// Pack WA[j][0:1024]=w_ih[j], WA[j][1024:1536]=w_hh[j]  (j<1024)
__global__ void k_pack(const float* __restrict__ w_ih, const float* __restrict__ w_hh) {
    int j = blockIdx.x;                 // 1024 blocks
    int tid = threadIdx.x;              // 128 threads
    const float4* sih = reinterpret_cast<const float4*>(w_ih + (size_t)j * 1024);
    const float4* shh = reinterpret_cast<const float4*>(w_hh + (size_t)j * 512);
    float4* dst = reinterpret_cast<float4*>(g_WA + (size_t)j * 1536);
    for (int i = tid; i < 256; i += 128) dst[i] = sih[i];
    for (int i = tid; i < 128; i += 128) dst[256 + i] = shh[i];
}

// -------------------------------------------------------------------------
// h0[b,e] = tanh(sent[b,0,512:] @ h0_w[e,:] + h0_b[e]) -> xT rows 1024..1535
// also zero xT rows 0..1023 (s_prev = 0 for iter 0)
__global__ void k_init(const float* __restrict__ sent, const float* __restrict__ h0w,
                       const float* __restrict__ h0b) {
    int b = blockIdx.x;                 // 128 blocks
    int tid = threadIdx.x;              // 256 threads
    __shared__ float xs[512];
    const float* lb = sent + (size_t)b * LL * D2 + 512;
    for (int i = tid; i < 512; i += 256) xs[i] = lb[i];
    for (int k = tid; k < 1024; k += 256) g_xT[(size_t)k * BB + b] = 0.f;
    __syncthreads();
    for (int e = tid; e < 512; e += 256) {
        const float4* wr = reinterpret_cast<const float4*>(h0w + (size_t)e * 512);
        float s = 0.f;
        #pragma unroll 8
        for (int i = 0; i < 128; i++) {
            float4 w = wr[i];
            float4 x = *reinterpret_cast<const float4*>(&xs[i * 4]);
            s = fmaf(w.x, x.x, s); s = fmaf(w.y, x.y, s);
            s = fmaf(w.z, x.z, s); s = fmaf(w.w, x.w, s);
        }
        g_xT[(size_t)(1024 + e) * BB + b] = tanhf(s + h0b[e]);
    }
}

// -------------------------------------------------------------------------
// d_proj = sent @ wd^T + bd : SGEMM M=25600 N=512 K=1024, C[m][n] row-major.
// 128x128 block tile, k-chunk 8, 256 threads, 8x8 per thread (as 8x4 f32x2),
// double buffered, inner product on packed FFMA2.
__global__ __launch_bounds__(256) void k_dproj(const float* __restrict__ Ag,
                                               const float* __restrict__ Wg,
                                               const float* __restrict__ bd,
                                               float* __restrict__ C) {
    __shared__ float As[2][8][132];
    __shared__ float Bs[2][8][132];
    const int m0 = blockIdx.x * 128;
    const int n0 = blockIdx.y * 128;
    const int tid = threadIdx.x;
    const int lrow = tid >> 1;
    const int lq = (tid & 1);           // float4 quarter: k offset lq*4
    const float4* Aro = reinterpret_cast<const float4*>(Ag + (size_t)(m0 + lrow) * 1024);
    const float4* Wro = reinterpret_cast<const float4*>(Wg + (size_t)(n0 + lrow) * 1024);
    const int tx = tid & 15, ty = tid >> 4;

    unsigned long long acc2[8][4];      // [i][j-pair] packed fp32x2 accumulators
    #pragma unroll
    for (int i = 0; i < 8; i++)
        #pragma unroll
        for (int j = 0; j < 4; j++) acc2[i][j] = 0ull;

    float4 a_ld = Aro[lq];
    float4 w_ld = Wro[lq];
    As[0][lq * 4 + 0][lrow] = a_ld.x; As[0][lq * 4 + 1][lrow] = a_ld.y;
    As[0][lq * 4 + 2][lrow] = a_ld.z; As[0][lq * 4 + 3][lrow] = a_ld.w;
    Bs[0][lq * 4 + 0][lrow] = w_ld.x; Bs[0][lq * 4 + 1][lrow] = w_ld.y;
    Bs[0][lq * 4 + 2][lrow] = w_ld.z; Bs[0][lq * 4 + 3][lrow] = w_ld.w;
    __syncthreads();

    int buf = 0;
    for (int k0 = 0; k0 < 1024; k0 += 8) {
        const bool more = (k0 + 8) < 1024;
        if (more) {
            a_ld = Aro[((k0 + 8) >> 2) + lq];
            w_ld = Wro[((k0 + 8) >> 2) + lq];
        }
        #pragma unroll
        for (int kk = 0; kk < 8; kk++) {
            float4 a0 = *reinterpret_cast<const float4*>(&As[buf][kk][ty * 4]);
            float4 a1 = *reinterpret_cast<const float4*>(&As[buf][kk][64 + ty * 4]);
            float4 b0 = *reinterpret_cast<const float4*>(&Bs[buf][kk][tx * 4]);
            float4 b1 = *reinterpret_cast<const float4*>(&Bs[buf][kk][64 + tx * 4]);
            unsigned long long bp0 = pk2(b0.x, b0.y);
            unsigned long long bp1 = pk2(b0.z, b0.w);
            unsigned long long bp2 = pk2(b1.x, b1.y);
            unsigned long long bp3 = pk2(b1.z, b1.w);
            float av[8] = {a0.x, a0.y, a0.z, a0.w, a1.x, a1.y, a1.z, a1.w};
            #pragma unroll
            for (int i = 0; i < 8; i++) {
                unsigned long long ad = pk2(av[i], av[i]);
                ffma2(acc2[i][0], ad, bp0);
                ffma2(acc2[i][1], ad, bp1);
                ffma2(acc2[i][2], ad, bp2);
                ffma2(acc2[i][3], ad, bp3);
            }
        }
        if (more) {
            int nb = buf ^ 1;
            As[nb][lq * 4 + 0][lrow] = a_ld.x; As[nb][lq * 4 + 1][lrow] = a_ld.y;
            As[nb][lq * 4 + 2][lrow] = a_ld.z; As[nb][lq * 4 + 3][lrow] = a_ld.w;
            Bs[nb][lq * 4 + 0][lrow] = w_ld.x; Bs[nb][lq * 4 + 1][lrow] = w_ld.y;
            Bs[nb][lq * 4 + 2][lrow] = w_ld.z; Bs[nb][lq * 4 + 3][lrow] = w_ld.w;
            __syncthreads();
            buf = nb;
        }
    }

    float bn[8];
    #pragma unroll
    for (int j = 0; j < 4; j++) {
        bn[j]     = bd[n0 + tx * 4 + j];
        bn[4 + j] = bd[n0 + 64 + tx * 4 + j];
    }
    #pragma unroll
    for (int i = 0; i < 8; i++) {
        int m = m0 + ((i < 4) ? (ty * 4 + i) : (64 + ty * 4 + i - 4));
        float* crow = C + (size_t)m * 512 + n0;
        float2 p0 = upk(acc2[i][0]);
        float2 p1 = upk(acc2[i][1]);
        float2 p2 = upk(acc2[i][2]);
        float2 p3 = upk(acc2[i][3]);
        float4 v0 = make_float4(p0.x + bn[0], p0.y + bn[1], p1.x + bn[2], p1.y + bn[3]);
        float4 v1 = make_float4(p2.x + bn[4], p2.y + bn[5], p3.x + bn[6], p3.y + bn[7]);
        *reinterpret_cast<float4*>(crow + tx * 4) = v0;
        *reinterpret_cast<float4*>(crow + 64 + tx * 4) = v1;
    }
}

// -------------------------------------------------------------------------
// Small "tall-skinny" GEMM body over a K-slice: acc[j][b] = sum_{k in slice}.
// Block: 256 threads = (b = tid&127) x (jj = tid>>7 in {0,1}); JT = 2*JPT j's.
template <int JPT>
__device__ __forceinline__ void gemm_cols(const float* __restrict__ W, int K,
                                          int kc0, int kcnt,
                                          const float* __restrict__ xcol,
                                          int b, int jj, float acc[JPT], float* Ws) {
    const int JT = 2 * JPT;
    #pragma unroll
    for (int u = 0; u < JPT; u++) acc[u] = 0.f;
    for (int kc = kc0; kc < kc0 + kcnt; kc += 64) {
        __syncthreads();
        for (int i = threadIdx.x; i < JT * 16; i += blockDim.x) {
            int j = i >> 4, kq = i & 15;
            *reinterpret_cast<float4*>(Ws + j * 64 + kq * 4) =
                *reinterpret_cast<const float4*>(W + (size_t)j * K + kc + kq * 4);
        }
        __syncthreads();
        #pragma unroll 4
        for (int k = 0; k < 64; k += 4) {
            float x0 = xcol[(size_t)(kc + k + 0) * BB + b];
            float x1 = xcol[(size_t)(kc + k + 1) * BB + b];
            float x2 = xcol[(size_t)(kc + k + 2) * BB + b];
            float x3 = xcol[(size_t)(kc + k + 3) * BB + b];
            #pragma unroll
            for (int u = 0; u < JPT; u++) {
                float4 w = *reinterpret_cast<const float4*>(Ws + (jj * JPT + u) * 64 + k);
                acc[u] = fmaf(w.x, x0, acc[u]);
                acc[u] = fmaf(w.y, x1, acc[u]);
                acc[u] = fmaf(w.z, x2, acc[u]);
                acc[u] = fmaf(w.w, x3, acc[u]);
            }
        }
    }
}

// gates split-K x4: grid (128 jblocks, 4 ksplits). Partials -> g_part[ks][row][b].
// segA (jb<64): combined rz rows j<1024, K=1536 packed WA, x = [s_prev|h]
// segB (64..95): xn rows 1024..1535 (w_ih rows 1024.., K=1024, x = s_prev)
// segC (96..127): hn rows -> part rows 1536..2047 (w_hh rows 1024.., K=512, x = h)
__global__ __launch_bounds__(256) void k_gates(const float* __restrict__ w_ih,
                                               const float* __restrict__ w_hh) {
    __shared__ float Ws[16 * 64];
    const int jb = blockIdx.x;           // 128
    const int ks = blockIdx.y;           // 4
    const int tid = threadIdx.x;
    const int b = tid & 127, jj = tid >> 7;
    const float* W; const float* xcol;
    int K, outj;
    if (jb < 64) {
        int j0 = jb * 16;
        W = g_WA + (size_t)j0 * 1536; K = 1536; xcol = g_xT; outj = j0;
    } else if (jb < 96) {
        int j0 = 1024 + (jb - 64) * 16;
        W = w_ih + (size_t)j0 * 1024; K = 1024; xcol = g_xT; outj = j0;
    } else {
        int j0 = 1024 + (jb - 96) * 16;
        W = w_hh + (size_t)j0 * 512; K = 512; xcol = g_xT + (size_t)1024 * BB;
        outj = 512 + j0;                 // rows 1536..2047
    }
    const int kper = K >> 2;
    float acc[8];
    gemm_cols<8>(W, K, ks * kper, kper, xcol, b, jj, acc, Ws);
    float* P = g_part + (size_t)ks * 2048 * BB;
    #pragma unroll
    for (int u = 0; u < 8; u++) {
        int jl = jj * 8 + u;
        P[(size_t)(outj + jl) * BB + b] = acc[u];
    }
}

// GRU combine: sum split-K partials + biases, h' = (1-z)*n + z*h (in place in xT)
__global__ void k_comb(const float* __restrict__ b_ih, const float* __restrict__ b_hh) {
    int gid = blockIdx.x * blockDim.x + threadIdx.x;   // 65536
    if (gid >= BB * EH) return;
    int b = gid & 127, e = gid >> 7;
    float rg = b_ih[e] + b_hh[e];
    float zg = b_ih[512 + e] + b_hh[512 + e];
    float xn = b_ih[1024 + e];
    float hn = b_hh[1024 + e];
    #pragma unroll
    for (int ks = 0; ks < 4; ks++) {
        const float* P = g_part + (size_t)ks * 2048 * BB;
        rg += P[(size_t)e * BB + b];
        zg += P[(size_t)(512 + e) * BB + b];
        xn += P[(size_t)(1024 + e) * BB + b];
        hn += P[(size_t)(1536 + e) * BB + b];
    }
    float hv = g_xT[(size_t)(1024 + e) * BB + b];
    float r = 1.f / (1.f + expf(-rg));
    float z = 1.f / (1.f + expf(-zg));
    float n = tanhf(fmaf(r, hn, xn));
    g_xT[(size_t)(1024 + e) * BB + b] = fmaf(1.f - z, n, z * hv);
}

// q partials: grid (64 jblocks, 4 ksplits), K=512
__global__ __launch_bounds__(256) void k_q(const float* __restrict__ wq) {
    __shared__ float Ws[8 * 64];
    const int j0 = blockIdx.x * 8;       // 64 jblocks
    const int ks = blockIdx.y;           // 4
    const int tid = threadIdx.x;
    const int b = tid & 127, jj = tid >> 7;
    float acc[4];
    gemm_cols<4>(wq + (size_t)j0 * 512, 512, ks * 128, 128,
                 g_xT + (size_t)1024 * BB, b, jj, acc, Ws);
    float* P = g_qpart + (size_t)ks * BB * AA;
    #pragma unroll
    for (int u = 0; u < 4; u++) {
        int jl = jj * 4 + u;
        P[(size_t)b * 512 + j0 + jl] = acc[u];
    }
}

// q[b][a] = sum_ks qpart + bq[a]
__global__ void k_qsum(const float* __restrict__ bq) {
    int gid = blockIdx.x * blockDim.x + threadIdx.x;   // 65536
    if (gid >= BB * AA) return;
    int a = gid & 511;
    float s = bq[a];
    #pragma unroll
    for (int ks = 0; ks < 4; ks++) s += g_qpart[(size_t)ks * BB * AA + gid];
    g_q[gid] = s;
}

// score[b,l] = ws . tanh(q[b] + d_proj[b,l]) + bs, with mask -> out scores
__global__ __launch_bounds__(256) void k_score(const float* __restrict__ ws,
                                               const float* __restrict__ bsp,
                                               int t, float* __restrict__ outs) {
    const int b = blockIdx.x / 25;
    const int lg = blockIdx.x % 25;
    const int w = threadIdx.x >> 5, lane = threadIdx.x & 31;
    const int l = lg * 8 + w;
    const float4* dp = reinterpret_cast<const float4*>(g_dproj + (size_t)(b * LL + l) * AA);
    const float4* qv = reinterpret_cast<const float4*>(g_q + (size_t)b * AA);
    const float4* wv = reinterpret_cast<const float4*>(ws);
    float acc = 0.f;
    #pragma unroll
    for (int i = 0; i < 4; i++) {
        float4 d = dp[lane + 32 * i];
        float4 q = qv[lane + 32 * i];
        float4 s = wv[lane + 32 * i];
        acc = fmaf(s.x, tanh_fast(d.x + q.x), acc);
        acc = fmaf(s.y, tanh_fast(d.y + q.y), acc);
        acc = fmaf(s.z, tanh_fast(d.z + q.z), acc);
        acc = fmaf(s.w, tanh_fast(d.w + q.w), acc);
    }
    #pragma unroll
    for (int off = 16; off; off >>= 1) acc += __shfl_xor_sync(0xffffffffu, acc, off);
    if (lane == 0) {
        float s = acc + bsp[0];
        for (int tt = 0; tt < t; tt++)
            if (g_idx[b * TT + tt] == l) s = -1000000.0f;
        outs[((size_t)b * TT + t) * LL + l] = s;
    }
}

// argmax per b (first-max tie break), record idx, gather selected sentence
__global__ void k_argmax(int t, const float* __restrict__ sent,
                         const float* __restrict__ outs, float* __restrict__ out_sel) {
    const int b = blockIdx.x, tid = threadIdx.x;   // 128 blocks x 256
    const float* sc = outs + ((size_t)b * TT + t) * LL;
    float bv = -3.0e38f; int bi = 0;
    for (int l = tid; l < LL; l += 256) {
        float v = sc[l];
        if (v > bv) { bv = v; bi = l; }
    }
    __shared__ float sv[256]; __shared__ int si[256];
    sv[tid] = bv; si[tid] = bi; __syncthreads();
    for (int s = 128; s > 0; s >>= 1) {
        if (tid < s) {
            if (sv[tid + s] > sv[tid] || (sv[tid + s] == sv[tid] && si[tid + s] < si[tid])) {
                sv[tid] = sv[tid + s]; si[tid] = si[tid + s];
            }
        }
        __syncthreads();
    }
    const int idx = si[0];
    if (tid == 0) { g_idx[b * TT + t] = idx; out_sel[b * TT + t] = (float)idx; }
    const float* srow = sent + ((size_t)(b * LL) + idx) * D2;
    for (int k = tid; k < D2; k += 256) g_xT[(size_t)k * BB + b] = srow[k];
}

// -------------------------------------------------------------------------
extern "C" void kernel_launch(void* const* d_in, const int* in_sizes, int n_in,
                              void* d_out, int out_size) {
    const float* sent = (const float*)d_in[0];
    const float* h0w  = (const float*)d_in[1];
    const float* h0b  = (const float*)d_in[2];
    const float* w_ih = (const float*)d_in[3];
    const float* w_hh = (const float*)d_in[4];
    const float* b_ih = (const float*)d_in[5];
    const float* b_hh = (const float*)d_in[6];
    const float* wq   = (const float*)d_in[7];
    const float* bq   = (const float*)d_in[8];
    const float* wd   = (const float*)d_in[9];
    const float* bd   = (const float*)d_in[10];
    const float* ws   = (const float*)d_in[11];
    const float* bsp  = (const float*)d_in[12];
    (void)in_sizes; (void)n_in; (void)out_size;

    float* out = (float*)d_out;
    float* out_scores = out;                      // B*T*L floats
    float* out_sel = out + (size_t)BB * TT * LL;  // B*T floats (indices as float)

    float* dproj_ptr = nullptr;
    cudaGetSymbolAddress((void**)&dproj_ptr, g_dproj);

    k_pack<<<1024, 128>>>(w_ih, w_hh);
    k_init<<<BB, 256>>>(sent, h0w, h0b);
    k_dproj<<<dim3(200, 4), 256>>>(sent, wd, bd, dproj_ptr);
    for (int t = 0; t < TT; t++) {
        k_gates<<<dim3(128, 4), 256>>>(w_ih, w_hh);
        k_comb<<<256, 256>>>(b_ih, b_hh);
        k_q<<<dim3(64, 4), 256>>>(wq);
        k_qsum<<<256, 256>>>(bq);
        k_score<<<BB * 25, 256>>>(ws, bsp, t, out_scores);
        k_argmax<<<BB, 256>>>(t, sent, out_scores, out_sel);
    }
}

// round 7
// speedup vs baseline: 1.7283x; 1.2332x over previous
#include <cuda_runtime.h>
#include <cuda_bf16.h>
#include <math.h>
#include <stdint.h>

// Problem constants
#define BB 128
#define LL 200
#define D2 1024   // 2*SH
#define EH 512
#define AA 512
#define TT 3

#define NSPLIT 8  // split-K for small GEMMs

// -------- device scratch (allocation-free rule: __device__ globals) --------
__device__ float g_dproj[(size_t)BB * LL * AA];     // 52.4 MB  [m][a], m=b*L+l
__device__ float g_xT[1536 * BB];                   // [k][b]: 0..1023 s_prev, 1024..1535 h
__device__ float g_part[NSPLIT * 2048 * BB];        // split-K partials [ks][row][b]
__device__ float g_qpart[NSPLIT * BB * AA];         // split-K partials for q
__device__ float g_q[BB * AA];                      // [b][a]
__device__ float g_WA[1024 * 1536];                 // packed [w_ih | w_hh] rows j<1024
__device__ int   g_idx[BB * TT];

// ---------------- small helpers ----------------
__device__ __forceinline__ float tanh_fast(float x) {
    float y;
    asm("tanh.approx.f32 %0, %1;" : "=f"(y) : "f"(x));
    return y;
}
__device__ __forceinline__ uint32_t smem_u32(const void* p) {
    uint32_t a;
    asm("{ .reg .u64 t; cvta.to.shared.u64 t, %1; cvt.u32.u64 %0, t; }" : "=r"(a) : "l"(p));
    return a;
}
// pack two fp32 -> bf16x2 (lo half = first arg), rn
__device__ __forceinline__ uint32_t pkbf(float lo, float hi) {
    uint32_t r;
    asm("cvt.rn.bf16x2.f32 %0, %1, %2;" : "=r"(r) : "f"(hi), "f"(lo));
    return r;
}
__device__ __forceinline__ float bf_lo(uint32_t v) { return __uint_as_float(v << 16); }
__device__ __forceinline__ float bf_hi(uint32_t v) { return __uint_as_float(v & 0xffff0000u); }

// ---------------- warp-level MMA plumbing (baseline PTX, no 'a' features) --
__device__ __forceinline__ void ldmx4(uint32_t* r, uint32_t addr) {
    asm volatile("ldmatrix.sync.aligned.m8n8.x4.shared.b16 {%0,%1,%2,%3}, [%4];"
                 : "=r"(r[0]), "=r"(r[1]), "=r"(r[2]), "=r"(r[3]) : "r"(addr));
}
__device__ __forceinline__ void mma_bf16(float* c, const uint32_t* a,
                                         uint32_t b0, uint32_t b1) {
    asm volatile("mma.sync.aligned.m16n8k16.row.col.f32.bf16.bf16.f32 "
                 "{%0,%1,%2,%3}, {%4,%5,%6,%7}, {%8,%9}, {%0,%1,%2,%3};"
                 : "+f"(c[0]), "+f"(c[1]), "+f"(c[2]), "+f"(c[3])
                 : "r"(a[0]), "r"(a[1]), "r"(a[2]), "r"(a[3]), "r"(b0), "r"(b1));
}

// -------------------------------------------------------------------------
// Pack WA[j][0:1024]=w_ih[j], WA[j][1024:1536]=w_hh[j]  (j<1024)
__global__ void k_pack(const float* __restrict__ w_ih, const float* __restrict__ w_hh) {
    int j = blockIdx.x;
    int tid = threadIdx.x;
    const float4* sih = reinterpret_cast<const float4*>(w_ih + (size_t)j * 1024);
    const float4* shh = reinterpret_cast<const float4*>(w_hh + (size_t)j * 512);
    float4* dst = reinterpret_cast<float4*>(g_WA + (size_t)j * 1536);
    for (int i = tid; i < 256; i += 128) dst[i] = sih[i];
    for (int i = tid; i < 128; i += 128) dst[256 + i] = shh[i];
}

// -------------------------------------------------------------------------
// h0 init + zero s_prev columns
__global__ void k_init(const float* __restrict__ sent, const float* __restrict__ h0w,
                       const float* __restrict__ h0b) {
    int b = blockIdx.x;
    int tid = threadIdx.x;
    __shared__ float xs[512];
    const float* lb = sent + (size_t)b * LL * D2 + 512;
    for (int i = tid; i < 512; i += 256) xs[i] = lb[i];
    for (int k = tid; k < 1024; k += 256) g_xT[(size_t)k * BB + b] = 0.f;
    __syncthreads();
    for (int e = tid; e < 512; e += 256) {
        const float4* wr = reinterpret_cast<const float4*>(h0w + (size_t)e * 512);
        float s = 0.f;
        #pragma unroll 8
        for (int i = 0; i < 128; i++) {
            float4 w = wr[i];
            float4 x = *reinterpret_cast<const float4*>(&xs[i * 4]);
            s = fmaf(w.x, x.x, s); s = fmaf(w.y, x.y, s);
            s = fmaf(w.z, x.z, s); s = fmaf(w.w, x.w, s);
        }
        g_xT[(size_t)(1024 + e) * BB + b] = tanhf(s + h0b[e]);
    }
}

// -------------------------------------------------------------------------
// d_proj = sent @ wd^T + bd via bf16 3-term split on mma.sync (m16n8k16).
// C[25600x512], tile 128x128 per CTA, k-chunk 32, 8 warps (warp tile 32x64).
// smem tiles: Ah, Al, Bh, Bl; 128 rows x 32 bf16, pitch 40 bf16 (80 B).
#define TPITCH 80                       // bytes per smem row
#define TSZ (128 * TPITCH)              // 10240 B per tile

__global__ __launch_bounds__(256) void k_dproj(const float* __restrict__ Ag,
                                               const float* __restrict__ Wg,
                                               const float* __restrict__ bd,
                                               float* __restrict__ C) {
    __shared__ uint16_t sm[4][TSZ / 2];  // Ah, Al, Bh, Bl
    const int tid = threadIdx.x;
    const int lane = tid & 31, warp = tid >> 5;
    const int wm = warp >> 1, wn = warp & 1;      // warp tile: rows wm*32, cols wn*64
    const int m0 = blockIdx.x * 128, n0 = blockIdx.y * 128;
    const uint32_t sb = smem_u32(sm);

    // staging: row = tid&127 handles 16 floats at khalf*16
    const int srow = tid & 127, shalf = tid >> 7;
    const float4* Ag4 = reinterpret_cast<const float4*>(
        Ag + (size_t)(m0 + srow) * 1024) + shalf * 4;
    const float4* Wg4 = reinterpret_cast<const float4*>(
        Wg + (size_t)(n0 + srow) * 1024) + shalf * 4;

    float acc[2][8][4];
    #pragma unroll
    for (int i = 0; i < 2; i++)
        #pragma unroll
        for (int j = 0; j < 8; j++)
            #pragma unroll
            for (int k = 0; k < 4; k++) acc[i][j][k] = 0.f;

    float4 ra[4], rb[4];
    #pragma unroll
    for (int i = 0; i < 4; i++) { ra[i] = Ag4[i]; rb[i] = Wg4[i]; }

    // ldmatrix source addresses (per thread, constant across chunks except kk)
    const uint32_t a_base = sb + (uint32_t)(wm * 32 + (lane & 15)) * TPITCH
                            + ((lane >> 4) * 8) * 2;
    const uint32_t b_base = sb + 2 * TSZ + (uint32_t)(wn * 64 + (lane & 15)) * TPITCH
                            + ((lane >> 4) * 8) * 2;
    const uint32_t st_off = (uint32_t)srow * TPITCH + (uint32_t)shalf * 32;

    for (int c = 0; c < 32; c++) {
        // convert staged regs -> bf16 h/l tiles in smem
        #pragma unroll
        for (int i = 0; i < 4; i++) {
            float4 v = ra[i];
            uint32_t h0 = pkbf(v.x, v.y), h1 = pkbf(v.z, v.w);
            uint32_t l0 = pkbf(v.x - bf_lo(h0), v.y - bf_hi(h0));
            uint32_t l1 = pkbf(v.z - bf_lo(h1), v.w - bf_hi(h1));
            uint32_t* d = reinterpret_cast<uint32_t*>(
                reinterpret_cast<char*>(sm[0]) + st_off + i * 8);
            d[0] = h0; d[1] = h1;
            uint32_t* dl = reinterpret_cast<uint32_t*>(
                reinterpret_cast<char*>(sm[1]) + st_off + i * 8);
            dl[0] = l0; dl[1] = l1;
            float4 w = rb[i];
            uint32_t H0 = pkbf(w.x, w.y), H1 = pkbf(w.z, w.w);
            uint32_t L0 = pkbf(w.x - bf_lo(H0), w.y - bf_hi(H0));
            uint32_t L1 = pkbf(w.z - bf_lo(H1), w.w - bf_hi(H1));
            uint32_t* e = reinterpret_cast<uint32_t*>(
                reinterpret_cast<char*>(sm[2]) + st_off + i * 8);
            e[0] = H0; e[1] = H1;
            uint32_t* el = reinterpret_cast<uint32_t*>(
                reinterpret_cast<char*>(sm[3]) + st_off + i * 8);
            el[0] = L0; el[1] = L1;
        }
        __syncthreads();

        // prefetch next chunk into regs (hidden behind mma)
        if (c < 31) {
            Ag4 += 8; Wg4 += 8;
            #pragma unroll
            for (int i = 0; i < 4; i++) { ra[i] = Ag4[i]; rb[i] = Wg4[i]; }
        }

        // compute: 2 k-steps of 16
        #pragma unroll
        for (int kk = 0; kk < 2; kk++) {
            uint32_t ah[2][4], al[2][4];
            #pragma unroll
            for (int mi = 0; mi < 2; mi++) {
                uint32_t aa = a_base + (uint32_t)(mi * 16) * TPITCH + kk * 32;
                ldmx4(ah[mi], aa);
                ldmx4(al[mi], aa + TSZ);
            }
            #pragma unroll
            for (int np = 0; np < 4; np++) {
                uint32_t ba = b_base + (uint32_t)(np * 16) * TPITCH + kk * 32;
                uint32_t bh[4], bl[4];
                ldmx4(bh, ba);
                ldmx4(bl, ba + TSZ);
                #pragma unroll
                for (int mi = 0; mi < 2; mi++)
                    #pragma unroll
                    for (int nb = 0; nb < 2; nb++) {
                        float* cc = acc[mi][np * 2 + nb];
                        mma_bf16(cc, ah[mi], bh[nb], bh[nb + 2]);   // hh
                        mma_bf16(cc, ah[mi], bl[nb], bl[nb + 2]);   // hl
                        mma_bf16(cc, al[mi], bh[nb], bh[nb + 2]);   // lh
                    }
            }
        }
        __syncthreads();
    }

    // epilogue: add bias, store fp32
    #pragma unroll
    for (int mi = 0; mi < 2; mi++) {
        const int r = m0 + wm * 32 + mi * 16 + (lane >> 2);
        #pragma unroll
        for (int ni = 0; ni < 8; ni++) {
            const int cc = n0 + wn * 64 + ni * 8 + (lane & 3) * 2;
            const float b0 = bd[cc], b1 = bd[cc + 1];
            float2 v0 = make_float2(acc[mi][ni][0] + b0, acc[mi][ni][1] + b1);
            float2 v1 = make_float2(acc[mi][ni][2] + b0, acc[mi][ni][3] + b1);
            *reinterpret_cast<float2*>(C + (size_t)r * 512 + cc) = v0;
            *reinterpret_cast<float2*>(C + (size_t)(r + 8) * 512 + cc) = v1;
        }
    }
}

// -------------------------------------------------------------------------
// Small tall-skinny GEMM body over a K-slice (fp32, latency-optimized)
template <int JPT>
__device__ __forceinline__ void gemm_cols(const float* __restrict__ W, int K,
                                          int kc0, int kcnt,
                                          const float* __restrict__ xcol,
                                          int b, int jj, float acc[JPT], float* Ws) {
    const int JT = 2 * JPT;
    #pragma unroll
    for (int u = 0; u < JPT; u++) acc[u] = 0.f;
    for (int kc = kc0; kc < kc0 + kcnt; kc += 64) {
        __syncthreads();
        for (int i = threadIdx.x; i < JT * 16; i += blockDim.x) {
            int j = i >> 4, kq = i & 15;
            *reinterpret_cast<float4*>(Ws + j * 64 + kq * 4) =
                *reinterpret_cast<const float4*>(W + (size_t)j * K + kc + kq * 4);
        }
        __syncthreads();
        #pragma unroll 4
        for (int k = 0; k < 64; k += 4) {
            float x0 = xcol[(size_t)(kc + k + 0) * BB + b];
            float x1 = xcol[(size_t)(kc + k + 1) * BB + b];
            float x2 = xcol[(size_t)(kc + k + 2) * BB + b];
            float x3 = xcol[(size_t)(kc + k + 3) * BB + b];
            #pragma unroll
            for (int u = 0; u < JPT; u++) {
                float4 w = *reinterpret_cast<const float4*>(Ws + (jj * JPT + u) * 64 + k);
                acc[u] = fmaf(w.x, x0, acc[u]);
                acc[u] = fmaf(w.y, x1, acc[u]);
                acc[u] = fmaf(w.z, x2, acc[u]);
                acc[u] = fmaf(w.w, x3, acc[u]);
            }
        }
    }
}

// gates split-K x NSPLIT: grid (128 jblocks, NSPLIT)
__global__ __launch_bounds__(256) void k_gates(const float* __restrict__ w_ih,
                                               const float* __restrict__ w_hh) {
    __shared__ float Ws[16 * 64];
    const int jb = blockIdx.x;
    const int ks = blockIdx.y;
    const int tid = threadIdx.x;
    const int b = tid & 127, jj = tid >> 7;
    const float* W; const float* xcol;
    int K, outj;
    if (jb < 64) {
        int j0 = jb * 16;
        W = g_WA + (size_t)j0 * 1536; K = 1536; xcol = g_xT; outj = j0;
    } else if (jb < 96) {
        int j0 = 1024 + (jb - 64) * 16;
        W = w_ih + (size_t)j0 * 1024; K = 1024; xcol = g_xT; outj = j0;
    } else {
        int j0 = 1024 + (jb - 96) * 16;
        W = w_hh + (size_t)j0 * 512; K = 512; xcol = g_xT + (size_t)1024 * BB;
        outj = 512 + j0;
    }
    const int kper = K / NSPLIT;
    float acc[8];
    gemm_cols<8>(W, K, ks * kper, kper, xcol, b, jj, acc, Ws);
    float* P = g_part + (size_t)ks * 2048 * BB;
    #pragma unroll
    for (int u = 0; u < 8; u++) {
        int jl = jj * 8 + u;
        P[(size_t)(outj + jl) * BB + b] = acc[u];
    }
}

// GRU combine: sum partials + biases, h' = (1-z)*n + z*h
__global__ void k_comb(const float* __restrict__ b_ih, const float* __restrict__ b_hh) {
    int gid = blockIdx.x * blockDim.x + threadIdx.x;
    if (gid >= BB * EH) return;
    int b = gid & 127, e = gid >> 7;
    float rg = b_ih[e] + b_hh[e];
    float zg = b_ih[512 + e] + b_hh[512 + e];
    float xn = b_ih[1024 + e];
    float hn = b_hh[1024 + e];
    #pragma unroll
    for (int ks = 0; ks < NSPLIT; ks++) {
        const float* P = g_part + (size_t)ks * 2048 * BB;
        rg += P[(size_t)e * BB + b];
        zg += P[(size_t)(512 + e) * BB + b];
        xn += P[(size_t)(1024 + e) * BB + b];
        hn += P[(size_t)(1536 + e) * BB + b];
    }
    float hv = g_xT[(size_t)(1024 + e) * BB + b];
    float r = 1.f / (1.f + expf(-rg));
    float z = 1.f / (1.f + expf(-zg));
    float n = tanhf(fmaf(r, hn, xn));
    g_xT[(size_t)(1024 + e) * BB + b] = fmaf(1.f - z, n, z * hv);
}

// q partials: grid (64 jblocks, NSPLIT), K=512
__global__ __launch_bounds__(256) void k_q(const float* __restrict__ wq) {
    __shared__ float Ws[8 * 64];
    const int j0 = blockIdx.x * 8;
    const int ks = blockIdx.y;
    const int tid = threadIdx.x;
    const int b = tid & 127, jj = tid >> 7;
    const int kper = 512 / NSPLIT;
    float acc[4];
    gemm_cols<4>(wq + (size_t)j0 * 512, 512, ks * kper, kper,
                 g_xT + (size_t)1024 * BB, b, jj, acc, Ws);
    float* P = g_qpart + (size_t)ks * BB * AA;
    #pragma unroll
    for (int u = 0; u < 4; u++) {
        int jl = jj * 4 + u;
        P[(size_t)b * 512 + j0 + jl] = acc[u];
    }
}

__global__ void k_qsum(const float* __restrict__ bq) {
    int gid = blockIdx.x * blockDim.x + threadIdx.x;
    if (gid >= BB * AA) return;
    int a = gid & 511;
    float s = bq[a];
    #pragma unroll
    for (int ks = 0; ks < NSPLIT; ks++) s += g_qpart[(size_t)ks * BB * AA + gid];
    g_q[gid] = s;
}

// score[b,l] = ws . tanh(q[b] + d_proj[b,l]) + bs, masked
__global__ __launch_bounds__(256) void k_score(const float* __restrict__ ws,
                                               const float* __restrict__ bsp,
                                               int t, float* __restrict__ outs) {
    const int b = blockIdx.x / 25;
    const int lg = blockIdx.x % 25;
    const int w = threadIdx.x >> 5, lane = threadIdx.x & 31;
    const int l = lg * 8 + w;
    const float4* dp = reinterpret_cast<const float4*>(g_dproj + (size_t)(b * LL + l) * AA);
    const float4* qv = reinterpret_cast<const float4*>(g_q + (size_t)b * AA);
    const float4* wv = reinterpret_cast<const float4*>(ws);
    float acc = 0.f;
    #pragma unroll
    for (int i = 0; i < 4; i++) {
        float4 d = dp[lane + 32 * i];
        float4 q = qv[lane + 32 * i];
        float4 s = wv[lane + 32 * i];
        acc = fmaf(s.x, tanh_fast(d.x + q.x), acc);
        acc = fmaf(s.y, tanh_fast(d.y + q.y), acc);
        acc = fmaf(s.z, tanh_fast(d.z + q.z), acc);
        acc = fmaf(s.w, tanh_fast(d.w + q.w), acc);
    }
    #pragma unroll
    for (int off = 16; off; off >>= 1) acc += __shfl_xor_sync(0xffffffffu, acc, off);
    if (lane == 0) {
        float s = acc + bsp[0];
        for (int tt = 0; tt < t; tt++)
            if (g_idx[b * TT + tt] == l) s = -1000000.0f;
        outs[((size_t)b * TT + t) * LL + l] = s;
    }
}

// argmax per b, record idx, gather selected sentence into xT columns
__global__ void k_argmax(int t, const float* __restrict__ sent,
                         const float* __restrict__ outs, float* __restrict__ out_sel) {
    const int b = blockIdx.x, tid = threadIdx.x;
    const float* sc = outs + ((size_t)b * TT + t) * LL;
    float bv = -3.0e38f; int bi = 0;
    for (int l = tid; l < LL; l += 256) {
        float v = sc[l];
        if (v > bv) { bv = v; bi = l; }
    }
    __shared__ float sv[256]; __shared__ int si[256];
    sv[tid] = bv; si[tid] = bi; __syncthreads();
    for (int s = 128; s > 0; s >>= 1) {
        if (tid < s) {
            if (sv[tid + s] > sv[tid] || (sv[tid + s] == sv[tid] && si[tid + s] < si[tid])) {
                sv[tid] = sv[tid + s]; si[tid] = si[tid + s];
            }
        }
        __syncthreads();
    }
    const int idx = si[0];
    if (tid == 0) { g_idx[b * TT + t] = idx; out_sel[b * TT + t] = (float)idx; }
    const float* srow = sent + ((size_t)(b * LL) + idx) * D2;
    for (int k = tid; k < D2; k += 256) g_xT[(size_t)k * BB + b] = srow[k];
}

// -------------------------------------------------------------------------
extern "C" void kernel_launch(void* const* d_in, const int* in_sizes, int n_in,
                              void* d_out, int out_size) {
    const float* sent = (const float*)d_in[0];
    const float* h0w  = (const float*)d_in[1];
    const float* h0b  = (const float*)d_in[2];
    const float* w_ih = (const float*)d_in[3];
    const float* w_hh = (const float*)d_in[4];
    const float* b_ih = (const float*)d_in[5];
    const float* b_hh = (const float*)d_in[6];
    const float* wq   = (const float*)d_in[7];
    const float* bq   = (const float*)d_in[8];
    const float* wd   = (const float*)d_in[9];
    const float* bd   = (const float*)d_in[10];
    const float* ws   = (const float*)d_in[11];
    const float* bsp  = (const float*)d_in[12];
    (void)in_sizes; (void)n_in; (void)out_size;

    float* out = (float*)d_out;
    float* out_scores = out;
    float* out_sel = out + (size_t)BB * TT * LL;

    float* dproj_ptr = nullptr;
    cudaGetSymbolAddress((void**)&dproj_ptr, g_dproj);

    k_pack<<<1024, 128>>>(w_ih, w_hh);
    k_init<<<BB, 256>>>(sent, h0w, h0b);
    k_dproj<<<dim3(200, 4), 256>>>(sent, wd, bd, dproj_ptr);
    for (int t = 0; t < TT; t++) {
        k_gates<<<dim3(128, NSPLIT), 256>>>(w_ih, w_hh);
        k_comb<<<256, 256>>>(b_ih, b_hh);
        k_q<<<dim3(64, NSPLIT), 256>>>(wq);
        k_qsum<<<256, 256>>>(bq);
        k_score<<<BB * 25, 256>>>(ws, bsp, t, out_scores);
        k_argmax<<<BB, 256>>>(t, sent, out_scores, out_sel);
    }
}

// round 8
// speedup vs baseline: 1.8272x; 1.0572x over previous
#include <cuda_runtime.h>
#include <cuda_bf16.h>
#include <math.h>
#include <stdint.h>

// Problem constants
#define BB 128
#define LL 200
#define D2 1024   // 2*SH
#define EH 512
#define AA 512
#define TT 3

#define NSPLIT 8  // split-K for small GEMMs

// -------- device scratch (allocation-free rule: __device__ globals) --------
__device__ float g_dproj[(size_t)BB * LL * AA];     // 52.4 MB  [m][a], m=b*L+l
__device__ float g_xT[1536 * BB];                   // [k][b]: 0..1023 s_prev, 1024..1535 h
__device__ float g_part[NSPLIT * 2048 * BB];        // split-K partials [ks][row][b]
__device__ float g_qpart[NSPLIT * BB * AA];         // split-K partials for q
__device__ float g_q[BB * AA];                      // [b][a]
__device__ float g_WA[1024 * 1536];                 // packed [w_ih | w_hh] rows j<1024
__device__ int   g_idx[BB * TT];

// ---------------- small helpers ----------------
__device__ __forceinline__ float tanh_fast(float x) {
    float y;
    asm("tanh.approx.f32 %0, %1;" : "=f"(y) : "f"(x));
    return y;
}
__device__ __forceinline__ uint32_t smem_u32(const void* p) {
    uint32_t a;
    asm("{ .reg .u64 t; cvta.to.shared.u64 t, %1; cvt.u32.u64 %0, t; }" : "=r"(a) : "l"(p));
    return a;
}
// pack two fp32 -> bf16x2 (lo half = first arg), rn
__device__ __forceinline__ uint32_t pkbf(float lo, float hi) {
    uint32_t r;
    asm("cvt.rn.bf16x2.f32 %0, %1, %2;" : "=r"(r) : "f"(hi), "f"(lo));
    return r;
}
__device__ __forceinline__ float bf_lo(uint32_t v) { return __uint_as_float(v << 16); }
__device__ __forceinline__ float bf_hi(uint32_t v) { return __uint_as_float(v & 0xffff0000u); }

// ---------------- warp-level MMA plumbing (baseline PTX, no 'a' features) --
__device__ __forceinline__ void ldmx4(uint32_t* r, uint32_t addr) {
    asm volatile("ldmatrix.sync.aligned.m8n8.x4.shared.b16 {%0,%1,%2,%3}, [%4];"
                 : "=r"(r[0]), "=r"(r[1]), "=r"(r[2]), "=r"(r[3]) : "r"(addr));
}
__device__ __forceinline__ void mma_bf16(float* c, const uint32_t* a,
                                         uint32_t b0, uint32_t b1) {
    asm volatile("mma.sync.aligned.m16n8k16.row.col.f32.bf16.bf16.f32 "
                 "{%0,%1,%2,%3}, {%4,%5,%6,%7}, {%8,%9}, {%0,%1,%2,%3};"
                 : "+f"(c[0]), "+f"(c[1]), "+f"(c[2]), "+f"(c[3])
                 : "r"(a[0]), "r"(a[1]), "r"(a[2]), "r"(a[3]), "r"(b0), "r"(b1));
}

// -------------------------------------------------------------------------
// Pack WA[j][0:1024]=w_ih[j], WA[j][1024:1536]=w_hh[j]  (j<1024)
__global__ void k_pack(const float* __restrict__ w_ih, const float* __restrict__ w_hh) {
    int j = blockIdx.x;
    int tid = threadIdx.x;
    const float4* sih = reinterpret_cast<const float4*>(w_ih + (size_t)j * 1024);
    const float4* shh = reinterpret_cast<const float4*>(w_hh + (size_t)j * 512);
    float4* dst = reinterpret_cast<float4*>(g_WA + (size_t)j * 1536);
    for (int i = tid; i < 256; i += 128) dst[i] = sih[i];
    for (int i = tid; i < 128; i += 128) dst[256 + i] = shh[i];
}

// -------------------------------------------------------------------------
// h0 init + zero s_prev columns
__global__ void k_init(const float* __restrict__ sent, const float* __restrict__ h0w,
                       const float* __restrict__ h0b) {
    int b = blockIdx.x;
    int tid = threadIdx.x;
    __shared__ float xs[512];
    const float* lb = sent + (size_t)b * LL * D2 + 512;
    for (int i = tid; i < 512; i += 256) xs[i] = lb[i];
    for (int k = tid; k < 1024; k += 256) g_xT[(size_t)k * BB + b] = 0.f;
    __syncthreads();
    for (int e = tid; e < 512; e += 256) {
        const float4* wr = reinterpret_cast<const float4*>(h0w + (size_t)e * 512);
        float s = 0.f;
        #pragma unroll 8
        for (int i = 0; i < 128; i++) {
            float4 w = wr[i];
            float4 x = *reinterpret_cast<const float4*>(&xs[i * 4]);
            s = fmaf(w.x, x.x, s); s = fmaf(w.y, x.y, s);
            s = fmaf(w.z, x.z, s); s = fmaf(w.w, x.w, s);
        }
        g_xT[(size_t)(1024 + e) * BB + b] = tanhf(s + h0b[e]);
    }
}

// -------------------------------------------------------------------------
// d_proj = sent @ wd^T + bd via bf16 3-term split on mma.sync (m16n8k16).
// Tile 128x128 per CTA, k-chunk 32, 8 warps (warp tile 32x64).
// Double-buffered smem (dynamic, 2 x 4 tiles), ONE sync per chunk,
// __launch_bounds__(256,2) so 2 CTAs/SM overlap convert with mma.
// Grid (4, 200): n-tile = blockIdx.x, m-tile = blockIdx.y -> CTAs sharing an
// A m-tile are consecutive bids (same wave) -> A read from L2, not DRAM x4.
#define TPITCH 80                       // bytes per smem row (32 bf16 + pad)
#define TSZ (128 * TPITCH)              // 10240 B per tile
#define BUFSZ (4 * TSZ)                 // Ah, Al, Bh, Bl
#define SMEM_DP (2 * BUFSZ)             // 81920 B

__global__ __launch_bounds__(256, 2) void k_dproj(const float* __restrict__ Ag,
                                                  const float* __restrict__ Wg,
                                                  const float* __restrict__ bd,
                                                  float* __restrict__ C) {
    extern __shared__ char smdp[];
    const int tid = threadIdx.x;
    const int lane = tid & 31, warp = tid >> 5;
    const int wm = warp >> 1, wn = warp & 1;      // warp tile: rows wm*32, cols wn*64
    const int n0 = blockIdx.x * 128, m0 = blockIdx.y * 128;
    const uint32_t sb = smem_u32(smdp);

    // staging: row = tid&127 handles 16 floats at half = tid>>7
    const int srow = tid & 127, shalf = tid >> 7;
    const float4* Arow = reinterpret_cast<const float4*>(Ag + (size_t)(m0 + srow) * 1024);
    const float4* Wrow = reinterpret_cast<const float4*>(Wg + (size_t)(n0 + srow) * 1024);

    float acc[2][8][4];
    #pragma unroll
    for (int i = 0; i < 2; i++)
        #pragma unroll
        for (int j = 0; j < 8; j++)
            #pragma unroll
            for (int k = 0; k < 4; k++) acc[i][j][k] = 0.f;

    // ldmatrix base addresses within a buffer (add buf offset per chunk)
    const uint32_t a_rel = (uint32_t)(wm * 32 + (lane & 15)) * TPITCH + ((lane >> 4) * 8) * 2;
    const uint32_t b_rel = 2 * TSZ + (uint32_t)(wn * 64 + (lane & 15)) * TPITCH
                           + ((lane >> 4) * 8) * 2;
    const uint32_t st_off = (uint32_t)srow * TPITCH + (uint32_t)shalf * 32;

    // convert chunk c's 16 A-floats + 16 W-floats into smem buffer `base`
    auto convert = [&](int c, uint32_t base) {
        const float4* a4 = Arow + c * 8 + shalf * 4;
        const float4* w4 = Wrow + c * 8 + shalf * 4;
        char* sbase = smdp + base;
        #pragma unroll
        for (int i = 0; i < 4; i++) {
            float4 v = a4[i];
            uint32_t h0 = pkbf(v.x, v.y), h1 = pkbf(v.z, v.w);
            uint32_t l0 = pkbf(v.x - bf_lo(h0), v.y - bf_hi(h0));
            uint32_t l1 = pkbf(v.z - bf_lo(h1), v.w - bf_hi(h1));
            uint32_t* d = reinterpret_cast<uint32_t*>(sbase + st_off + i * 8);
            d[0] = h0; d[1] = h1;
            uint32_t* dl = reinterpret_cast<uint32_t*>(sbase + TSZ + st_off + i * 8);
            dl[0] = l0; dl[1] = l1;
        }
        #pragma unroll
        for (int i = 0; i < 4; i++) {
            float4 w = w4[i];
            uint32_t H0 = pkbf(w.x, w.y), H1 = pkbf(w.z, w.w);
            uint32_t L0 = pkbf(w.x - bf_lo(H0), w.y - bf_hi(H0));
            uint32_t L1 = pkbf(w.z - bf_lo(H1), w.w - bf_hi(H1));
            uint32_t* e = reinterpret_cast<uint32_t*>(sbase + 2 * TSZ + st_off + i * 8);
            e[0] = H0; e[1] = H1;
            uint32_t* el = reinterpret_cast<uint32_t*>(sbase + 3 * TSZ + st_off + i * 8);
            el[0] = L0; el[1] = L1;
        }
    };

    convert(0, 0);
    __syncthreads();

    for (int c = 0; c < 32; c++) {
        const uint32_t base = (uint32_t)(c & 1) * BUFSZ;
        // prefetch-convert next chunk into the other buffer (no hazard with
        // this chunk's mma reads; barrier below fences for next iteration)
        if (c < 31) convert(c + 1, ((c + 1) & 1) * BUFSZ);

        // compute chunk c: 2 k-steps of 16
        #pragma unroll
        for (int kk = 0; kk < 2; kk++) {
            uint32_t ah[2][4], al[2][4];
            #pragma unroll
            for (int mi = 0; mi < 2; mi++) {
                uint32_t aa = sb + base + a_rel + (uint32_t)(mi * 16) * TPITCH + kk * 32;
                ldmx4(ah[mi], aa);
                ldmx4(al[mi], aa + TSZ);
            }
            #pragma unroll
            for (int np = 0; np < 4; np++) {
                uint32_t ba = sb + base + b_rel + (uint32_t)(np * 16) * TPITCH + kk * 32;
                uint32_t bh[4], bl[4];
                ldmx4(bh, ba);
                ldmx4(bl, ba + TSZ);
                #pragma unroll
                for (int mi = 0; mi < 2; mi++)
                    #pragma unroll
                    for (int nb = 0; nb < 2; nb++) {
                        float* cc = acc[mi][np * 2 + nb];
                        mma_bf16(cc, ah[mi], bh[nb], bh[nb + 2]);   // hh
                        mma_bf16(cc, ah[mi], bl[nb], bl[nb + 2]);   // hl
                        mma_bf16(cc, al[mi], bh[nb], bh[nb + 2]);   // lh
                    }
            }
        }
        __syncthreads();
    }

    // epilogue: add bias, store fp32
    #pragma unroll
    for (int mi = 0; mi < 2; mi++) {
        const int r = m0 + wm * 32 + mi * 16 + (lane >> 2);
        #pragma unroll
        for (int ni = 0; ni < 8; ni++) {
            const int cc = n0 + wn * 64 + ni * 8 + (lane & 3) * 2;
            const float b0 = bd[cc], b1 = bd[cc + 1];
            float2 v0 = make_float2(acc[mi][ni][0] + b0, acc[mi][ni][1] + b1);
            float2 v1 = make_float2(acc[mi][ni][2] + b0, acc[mi][ni][3] + b1);
            *reinterpret_cast<float2*>(C + (size_t)r * 512 + cc) = v0;
            *reinterpret_cast<float2*>(C + (size_t)(r + 8) * 512 + cc) = v1;
        }
    }
}

// -------------------------------------------------------------------------
// Small tall-skinny GEMM body over a K-slice (fp32, latency-optimized)
template <int JPT>
__device__ __forceinline__ void gemm_cols(const float* __restrict__ W, int K,
                                          int kc0, int kcnt,
                                          const float* __restrict__ xcol,
                                          int b, int jj, float acc[JPT], float* Ws) {
    const int JT = 2 * JPT;
    #pragma unroll
    for (int u = 0; u < JPT; u++) acc[u] = 0.f;
    for (int kc = kc0; kc < kc0 + kcnt; kc += 64) {
        __syncthreads();
        for (int i = threadIdx.x; i < JT * 16; i += blockDim.x) {
            int j = i >> 4, kq = i & 15;
            *reinterpret_cast<float4*>(Ws + j * 64 + kq * 4) =
                *reinterpret_cast<const float4*>(W + (size_t)j * K + kc + kq * 4);
        }
        __syncthreads();
        #pragma unroll 4
        for (int k = 0; k < 64; k += 4) {
            float x0 = xcol[(size_t)(kc + k + 0) * BB + b];
            float x1 = xcol[(size_t)(kc + k + 1) * BB + b];
            float x2 = xcol[(size_t)(kc + k + 2) * BB + b];
            float x3 = xcol[(size_t)(kc + k + 3) * BB + b];
            #pragma unroll
            for (int u = 0; u < JPT; u++) {
                float4 w = *reinterpret_cast<const float4*>(Ws + (jj * JPT + u) * 64 + k);
                acc[u] = fmaf(w.x, x0, acc[u]);
                acc[u] = fmaf(w.y, x1, acc[u]);
                acc[u] = fmaf(w.z, x2, acc[u]);
                acc[u] = fmaf(w.w, x3, acc[u]);
            }
        }
    }
}

// gates split-K x NSPLIT: grid (128 jblocks, NSPLIT)
__global__ __launch_bounds__(256) void k_gates(const float* __restrict__ w_ih,
                                               const float* __restrict__ w_hh) {
    __shared__ float Ws[16 * 64];
    const int jb = blockIdx.x;
    const int ks = blockIdx.y;
    const int tid = threadIdx.x;
    const int b = tid & 127, jj = tid >> 7;
    const float* W; const float* xcol;
    int K, outj;
    if (jb < 64) {
        int j0 = jb * 16;
        W = g_WA + (size_t)j0 * 1536; K = 1536; xcol = g_xT; outj = j0;
    } else if (jb < 96) {
        int j0 = 1024 + (jb - 64) * 16;
        W = w_ih + (size_t)j0 * 1024; K = 1024; xcol = g_xT; outj = j0;
    } else {
        int j0 = 1024 + (jb - 96) * 16;
        W = w_hh + (size_t)j0 * 512; K = 512; xcol = g_xT + (size_t)1024 * BB;
        outj = 512 + j0;
    }
    const int kper = K / NSPLIT;
    float acc[8];
    gemm_cols<8>(W, K, ks * kper, kper, xcol, b, jj, acc, Ws);
    float* P = g_part + (size_t)ks * 2048 * BB;
    #pragma unroll
    for (int u = 0; u < 8; u++) {
        int jl = jj * 8 + u;
        P[(size_t)(outj + jl) * BB + b] = acc[u];
    }
}

// GRU combine: sum partials + biases, h' = (1-z)*n + z*h
__global__ void k_comb(const float* __restrict__ b_ih, const float* __restrict__ b_hh) {
    int gid = blockIdx.x * blockDim.x + threadIdx.x;
    if (gid >= BB * EH) return;
    int b = gid & 127, e = gid >> 7;
    float rg = b_ih[e] + b_hh[e];
    float zg = b_ih[512 + e] + b_hh[512 + e];
    float xn = b_ih[1024 + e];
    float hn = b_hh[1024 + e];
    #pragma unroll
    for (int ks = 0; ks < NSPLIT; ks++) {
        const float* P = g_part + (size_t)ks * 2048 * BB;
        rg += P[(size_t)e * BB + b];
        zg += P[(size_t)(512 + e) * BB + b];
        xn += P[(size_t)(1024 + e) * BB + b];
        hn += P[(size_t)(1536 + e) * BB + b];
    }
    float hv = g_xT[(size_t)(1024 + e) * BB + b];
    float r = 1.f / (1.f + expf(-rg));
    float z = 1.f / (1.f + expf(-zg));
    float n = tanhf(fmaf(r, hn, xn));
    g_xT[(size_t)(1024 + e) * BB + b] = fmaf(1.f - z, n, z * hv);
}

// q partials: grid (64 jblocks, NSPLIT), K=512
__global__ __launch_bounds__(256) void k_q(const float* __restrict__ wq) {
    __shared__ float Ws[8 * 64];
    const int j0 = blockIdx.x * 8;
    const int ks = blockIdx.y;
    const int tid = threadIdx.x;
    const int b = tid & 127, jj = tid >> 7;
    const int kper = 512 / NSPLIT;
    float acc[4];
    gemm_cols<4>(wq + (size_t)j0 * 512, 512, ks * kper, kper,
                 g_xT + (size_t)1024 * BB, b, jj, acc, Ws);
    float* P = g_qpart + (size_t)ks * BB * AA;
    #pragma unroll
    for (int u = 0; u < 4; u++) {
        int jl = jj * 4 + u;
        P[(size_t)b * 512 + j0 + jl] = acc[u];
    }
}

__global__ void k_qsum(const float* __restrict__ bq) {
    int gid = blockIdx.x * blockDim.x + threadIdx.x;
    if (gid >= BB * AA) return;
    int a = gid & 511;
    float s = bq[a];
    #pragma unroll
    for (int ks = 0; ks < NSPLIT; ks++) s += g_qpart[(size_t)ks * BB * AA + gid];
    g_q[gid] = s;
}

// score[b,l] = ws . tanh(q[b] + d_proj[b,l]) + bs, masked
__global__ __launch_bounds__(256) void k_score(const float* __restrict__ ws,
                                               const float* __restrict__ bsp,
                                               int t, float* __restrict__ outs) {
    const int b = blockIdx.x / 25;
    const int lg = blockIdx.x % 25;
    const int w = threadIdx.x >> 5, lane = threadIdx.x & 31;
    const int l = lg * 8 + w;
    const float4* dp = reinterpret_cast<const float4*>(g_dproj + (size_t)(b * LL + l) * AA);
    const float4* qv = reinterpret_cast<const float4*>(g_q + (size_t)b * AA);
    const float4* wv = reinterpret_cast<const float4*>(ws);
    float acc = 0.f;
    #pragma unroll
    for (int i = 0; i < 4; i++) {
        float4 d = dp[lane + 32 * i];
        float4 q = qv[lane + 32 * i];
        float4 s = wv[lane + 32 * i];
        acc = fmaf(s.x, tanh_fast(d.x + q.x), acc);
        acc = fmaf(s.y, tanh_fast(d.y + q.y), acc);
        acc = fmaf(s.z, tanh_fast(d.z + q.z), acc);
        acc = fmaf(s.w, tanh_fast(d.w + q.w), acc);
    }
    #pragma unroll
    for (int off = 16; off; off >>= 1) acc += __shfl_xor_sync(0xffffffffu, acc, off);
    if (lane == 0) {
        float s = acc + bsp[0];
        for (int tt = 0; tt < t; tt++)
            if (g_idx[b * TT + tt] == l) s = -1000000.0f;
        outs[((size_t)b * TT + t) * LL + l] = s;
    }
}

// argmax per b, record idx, gather selected sentence into xT columns
__global__ void k_argmax(int t, const float* __restrict__ sent,
                         const float* __restrict__ outs, float* __restrict__ out_sel) {
    const int b = blockIdx.x, tid = threadIdx.x;
    const float* sc = outs + ((size_t)b * TT + t) * LL;
    float bv = -3.0e38f; int bi = 0;
    for (int l = tid; l < LL; l += 256) {
        float v = sc[l];
        if (v > bv) { bv = v; bi = l; }
    }
    __shared__ float sv[256]; __shared__ int si[256];
    sv[tid] = bv; si[tid] = bi; __syncthreads();
    for (int s = 128; s > 0; s >>= 1) {
        if (tid < s) {
            if (sv[tid + s] > sv[tid] || (sv[tid + s] == sv[tid] && si[tid + s] < si[tid])) {
                sv[tid] = sv[tid + s]; si[tid] = si[tid + s];
            }
        }
        __syncthreads();
    }
    const int idx = si[0];
    if (tid == 0) { g_idx[b * TT + t] = idx; out_sel[b * TT + t] = (float)idx; }
    const float* srow = sent + ((size_t)(b * LL) + idx) * D2;
    for (int k = tid; k < D2; k += 256) g_xT[(size_t)k * BB + b] = srow[k];
}

// -------------------------------------------------------------------------
extern "C" void kernel_launch(void* const* d_in, const int* in_sizes, int n_in,
                              void* d_out, int out_size) {
    const float* sent = (const float*)d_in[0];
    const float* h0w  = (const float*)d_in[1];
    const float* h0b  = (const float*)d_in[2];
    const float* w_ih = (const float*)d_in[3];
    const float* w_hh = (const float*)d_in[4];
    const float* b_ih = (const float*)d_in[5];
    const float* b_hh = (const float*)d_in[6];
    const float* wq   = (const float*)d_in[7];
    const float* bq   = (const float*)d_in[8];
    const float* wd   = (const float*)d_in[9];
    const float* bd   = (const float*)d_in[10];
    const float* ws   = (const float*)d_in[11];
    const float* bsp  = (const float*)d_in[12];
    (void)in_sizes; (void)n_in; (void)out_size;

    float* out = (float*)d_out;
    float* out_scores = out;
    float* out_sel = out + (size_t)BB * TT * LL;

    float* dproj_ptr = nullptr;
    cudaGetSymbolAddress((void**)&dproj_ptr, g_dproj);

    static int smem_set = 0;
    if (!smem_set) {
        cudaFuncSetAttribute(k_dproj, cudaFuncAttributeMaxDynamicSharedMemorySize, SMEM_DP);
        smem_set = 1;
    }

    k_pack<<<1024, 128>>>(w_ih, w_hh);
    k_init<<<BB, 256>>>(sent, h0w, h0b);
    k_dproj<<<dim3(4, 200), 256, SMEM_DP>>>(sent, wd, bd, dproj_ptr);
    for (int t = 0; t < TT; t++) {
        k_gates<<<dim3(128, NSPLIT), 256>>>(w_ih, w_hh);
        k_comb<<<256, 256>>>(b_ih, b_hh);
        k_q<<<dim3(64, NSPLIT), 256>>>(wq);
        k_qsum<<<256, 256>>>(bq);
        k_score<<<BB * 25, 256>>>(ws, bsp, t, out_scores);
        k_argmax<<<BB, 256>>>(t, sent, out_scores, out_sel);
    }
}